// round 11
// baseline (speedup 1.0000x reference)
#include <cuda_runtime.h>
#include <cuda_bf16.h>
#include <math.h>
#include <stdint.h>

#define HH 128
#define WW 128
#define NB 4
#define HW (HH * WW)

// ---------------- scratch (static device arrays; no allocation) ------------
__device__ float g_bufA[NB * 64 * HW];      // NHWC64 feature buffer
__device__ float g_bufB[NB * 64 * HW];      // NHWC64 feature buffer
__device__ float g_offb[NB * 144 * HW];     // offsets, NCHW
__device__ float g_nhwc128[NB * 128 * HW];  // concat(neibor,target) NHWC128
__device__ float g_nhwcN[NB * 64 * HW];     // neibor NHWC64
__device__ uint32_t g_wph[73728];           // conv weights hi, packed bf16x2 words
__device__ uint32_t g_wpl[73728];           // conv weights lo, packed bf16x2 words
__device__ uint32_t g_dwph[18432];          // deform weights hi, packed
__device__ uint32_t g_dwpl[18432];          // deform weights lo, packed

// ---------------- helpers ---------------------------------------------------
// split a float pair into packed bf16x2 hi word + lo word (even elem low half)
__device__ __forceinline__ void split2(float v0, float v1,
                                       uint32_t& hw, uint32_t& lw) {
    __nv_bfloat16 h0 = __float2bfloat16_rn(v0);
    __nv_bfloat16 h1 = __float2bfloat16_rn(v1);
    float l0 = v0 - __bfloat162float(h0);
    float l1 = v1 - __bfloat162float(h1);
    __nv_bfloat162 hp = __halves2bfloat162(h0, h1);
    __nv_bfloat162 lp = __floats2bfloat162_rn(l0, l1);
    hw = *(uint32_t*)&hp;
    lw = *(uint32_t*)&lp;
}
__device__ __forceinline__ void mma16(float* c, const uint32_t* a,
                                      uint32_t b0, uint32_t b1) {
    asm volatile(
        "mma.sync.aligned.m16n8k16.row.col.f32.bf16.bf16.f32 "
        "{%0,%1,%2,%3}, {%4,%5,%6,%7}, {%8,%9}, {%0,%1,%2,%3};"
        : "+f"(c[0]), "+f"(c[1]), "+f"(c[2]), "+f"(c[3])
        : "r"(a[0]), "r"(a[1]), "r"(a[2]), "r"(a[3]), "r"(b0), "r"(b1));
}
__device__ __forceinline__ void mma8bf(float* c, uint32_t a0, uint32_t a1,
                                       uint32_t b0) {
    asm volatile(
        "mma.sync.aligned.m16n8k8.row.col.f32.bf16.bf16.f32 "
        "{%0,%1,%2,%3}, {%4,%5}, {%6}, {%0,%1,%2,%3};"
        : "+f"(c[0]), "+f"(c[1]), "+f"(c[2]), "+f"(c[3])
        : "r"(a0), "r"(a1), "r"(b0));
}
__device__ __forceinline__ void ldm_x4(uint32_t* r, uint32_t saddr) {
    asm volatile(
        "ldmatrix.sync.aligned.m8n8.x4.shared.b16 {%0,%1,%2,%3}, [%4];"
        : "=r"(r[0]), "=r"(r[1]), "=r"(r[2]), "=r"(r[3]) : "r"(saddr));
}
__device__ __forceinline__ void ldm_x2(uint32_t* r, uint32_t saddr) {
    asm volatile(
        "ldmatrix.sync.aligned.m8n8.x2.shared.b16 {%0,%1}, [%2];"
        : "=r"(r[0]), "=r"(r[1]) : "r"(saddr));
}

// ---------------------------------------------------------------------------
// Transforms
// ---------------------------------------------------------------------------
__global__ __launch_bounds__(256) void concat_nhwc128_kernel(
    const float* __restrict__ n, const float* __restrict__ t, float* __restrict__ out)
{
    int idx = blockIdx.x * 256 + threadIdx.x;   // NB*HW
    int b  = idx >> 14;
    int yx = idx & (HW - 1);
    const float* s0 = n + (size_t)b * 64 * HW + yx;
    const float* s1 = t + (size_t)b * 64 * HW + yx;
    float* o = out + (size_t)idx * 128;
#pragma unroll 8
    for (int c = 0; c < 64; c++) o[c] = s0[(size_t)c * HW];
#pragma unroll 8
    for (int c = 0; c < 64; c++) o[64 + c] = s1[(size_t)c * HW];
}

__global__ __launch_bounds__(256) void nhwc64_kernel(
    const float* __restrict__ in, float* __restrict__ out)
{
    int idx = blockIdx.x * 256 + threadIdx.x;
    int b  = idx >> 14;
    int yx = idx & (HW - 1);
    const float* s = in + (size_t)b * 64 * HW + yx;
    float* o = out + (size_t)idx * 64;
#pragma unroll 8
    for (int c = 0; c < 64; c++) o[c] = s[(size_t)c * HW];
}

// conv weight prep: w[oc][ic][3][3] -> packed bf16x2 hi/lo words laid out as
// [chunk ch][kg][oc][8 words], ch = (kpos, ich), kg = 16-ch half of the chunk.
__global__ void wprep_kernel(const float* __restrict__ w, uint32_t* __restrict__ wph,
                             uint32_t* __restrict__ wpl, int C_IN, int C_OUT)
{
    int i = blockIdx.x * 256 + threadIdx.x;
    int tot = C_OUT * C_IN * 9 / 2;
    if (i >= tot) return;
    int wd = i & 7;
    int t  = i >> 3;
    int oc = t % C_OUT;
    int t2 = t / C_OUT;
    int kg = t2 & 1;
    int ch = t2 >> 1;
    int ICH = C_IN / 32;
    int kpos = ch / ICH;
    int ich  = ch % ICH;
    int ic = ich * 32 + kg * 16 + wd * 2;
    float v0 = w[((size_t)oc * C_IN + ic) * 9 + kpos];
    float v1 = w[((size_t)oc * C_IN + ic + 1) * 9 + kpos];
    uint32_t hw, lw;
    split2(v0, v1, hw, lw);
    wph[i] = hw;
    wpl[i] = lw;
}

// deform weight prep: w[oc][ic][9] -> packed words [(dg*36 + k*4 + wp)*64 + oc]
__global__ void dwprep_kernel(const float* __restrict__ w, uint32_t* __restrict__ dwph,
                              uint32_t* __restrict__ dwpl)
{
    int i = blockIdx.x * 256 + threadIdx.x;
    if (i >= 8 * 36 * 64) return;
    int oc  = i & 63;
    int t   = i >> 6;
    int rem = t % 36;
    int dg  = t / 36;
    int k   = rem >> 2;
    int wp  = rem & 3;
    int ic0 = dg * 8 + wp * 2;
    float v0 = w[((size_t)oc * 64 + ic0) * 9 + k];
    float v1 = w[((size_t)oc * 64 + ic0 + 1) * 9 + k];
    uint32_t hw, lw;
    split2(v0, v1, hw, lw);
    dwph[i] = hw;
    dwpl[i] = lw;
}

// ---------------------------------------------------------------------------
// mma.sync bf16 implicit-GEMM 3x3 conv (unchanged from round 10 — verified win)
// ---------------------------------------------------------------------------
template <int N_OC, int C_IN, bool NHWC_OUT>
__global__ __launch_bounds__(256)
void conv_mma_kernel(const float* __restrict__ in, const uint32_t* __restrict__ wph,
                     const uint32_t* __restrict__ wpl, const float* __restrict__ bias,
                     float* __restrict__ out)
{
    extern __shared__ __align__(16) uint32_t SM[];
    constexpr int ICH  = C_IN / 32;            // ic-chunks per k position
    constexpr int RST  = 20;                   // word row stride
    constexpr int A_HI = 0;
    constexpr int A_LO = A_HI + 130 * RST;
    constexpr int B_HI = A_LO + 130 * RST;
    constexpr int B_LO = B_HI + 3 * N_OC * RST;
    constexpr int NA   = N_OC / 16;            // n-atoms per warp (9 or 4)

    const int tid  = threadIdx.x;
    const int lane = tid & 31;
    const int wid  = tid >> 5;
    const int m0   = (wid & 3) * 32;           // 4 M-tiles of 32 px
    const int n0   = (wid >> 2) * (N_OC / 2);  // 2 N-halves

    const int r = blockIdx.x;
    const int b = r >> 7;
    const int y = r & 127;

    const int quad = lane >> 3;                // ldmatrix lane decode
    const int lr   = lane & 7;

    float acc[2][NA][4];
#pragma unroll
    for (int m = 0; m < 2; m++)
#pragma unroll
        for (int na = 0; na < NA; na++)
#pragma unroll
            for (int q = 0; q < 4; q++) acc[m][na][q] = 0.0f;

    for (int dy = 0; dy < 3; dy++) {
        const int yy = y + dy - 1;
        const bool rv = (yy >= 0) && (yy < HH);

        for (int ich = 0; ich < ICH; ich++) {
            // ---- stage A: 130 px (x = -1..128) x 32 ch, hi/lo split ----
            for (int t = tid; t < 260; t += 256) {
                int p  = t >> 1;
                int kg = t & 1;
                int x  = p - 1;
                bool val = rv && (x >= 0) && (x < WW);
                const float4* src = (const float4*)(in +
                    (((size_t)b * HW + (size_t)yy * WW + x) * C_IN + ich * 32 + kg * 16));
                int abase = p * RST + kg * 8;
#pragma unroll
                for (int j = 0; j < 4; j++) {
                    float4 v = val ? src[j] : make_float4(0.f, 0.f, 0.f, 0.f);
                    uint32_t h0, l0, h1, l1;
                    split2(v.x, v.y, h0, l0);
                    split2(v.z, v.w, h1, l1);
                    *(uint2*)&SM[A_HI + abase + 2 * j] = make_uint2(h0, h1);
                    *(uint2*)&SM[A_LO + abase + 2 * j] = make_uint2(l0, l1);
                }
            }
            // ---- stage B: 3 k-positions of this ich (pre-packed copy) ----
            for (int t = tid; t < 3 * N_OC * 16; t += 256) {
                int kp  = t / (N_OC * 16);
                int rem = t - kp * (N_OC * 16);
                int n   = rem >> 4;
                int w16 = rem & 15;
                int kg  = w16 >> 3;
                int wd  = w16 & 7;
                int gsrc = ((((dy * 3 + kp) * ICH + ich) * 2 + kg) * N_OC + n) * 8 + wd;
                int o = (kp * N_OC + n) * RST + w16;
                SM[B_HI + o] = wph[gsrc];
                SM[B_LO + o] = wpl[gsrc];
            }
            __syncthreads();

            // ---- compute: 3 dx taps x 2 k16 groups ----
#pragma unroll
            for (int dx = 0; dx < 3; dx++) {
#pragma unroll
                for (int kg = 0; kg < 2; kg++) {
                    uint32_t ah[2][4], al[2][4];
#pragma unroll
                    for (int m = 0; m < 2; m++) {
                        int row = m0 + m * 16 + dx + (quad & 1) * 8 + lr;
                        int wi  = row * RST + kg * 8 + (quad >> 1) * 4;
                        ldm_x4(ah[m], (uint32_t)__cvta_generic_to_shared(&SM[A_HI + wi]));
                        ldm_x4(al[m], (uint32_t)__cvta_generic_to_shared(&SM[A_LO + wi]));
                    }
#pragma unroll
                    for (int p2 = 0; p2 < NA - 1; p2 += 2) {
                        int rowb = dx * N_OC + n0 + p2 * 8 + (quad >> 1) * 8 + lr;
                        int wi   = rowb * RST + kg * 8 + (quad & 1) * 4;
                        uint32_t bh[4], bl[4];
                        ldm_x4(bh, (uint32_t)__cvta_generic_to_shared(&SM[B_HI + wi]));
                        ldm_x4(bl, (uint32_t)__cvta_generic_to_shared(&SM[B_LO + wi]));
#pragma unroll
                        for (int m = 0; m < 2; m++) {
                            mma16(acc[m][p2], ah[m], bh[0], bh[1]);
                            mma16(acc[m][p2], ah[m], bl[0], bl[1]);
                            mma16(acc[m][p2], al[m], bh[0], bh[1]);
                            mma16(acc[m][p2 + 1], ah[m], bh[2], bh[3]);
                            mma16(acc[m][p2 + 1], ah[m], bl[2], bl[3]);
                            mma16(acc[m][p2 + 1], al[m], bh[2], bh[3]);
                        }
                    }
                    if (NA & 1) {              // tail n-atom (NA = 9)
                        int p2 = NA - 1;
                        int rowb = dx * N_OC + n0 + p2 * 8 + lr;
                        int wi   = rowb * RST + kg * 8 + (quad & 1) * 4;
                        uint32_t bh[2], bl[2];
                        ldm_x2(bh, (uint32_t)__cvta_generic_to_shared(&SM[B_HI + wi]));
                        ldm_x2(bl, (uint32_t)__cvta_generic_to_shared(&SM[B_LO + wi]));
#pragma unroll
                        for (int m = 0; m < 2; m++) {
                            mma16(acc[m][p2], ah[m], bh[0], bh[1]);
                            mma16(acc[m][p2], ah[m], bl[0], bl[1]);
                            mma16(acc[m][p2], al[m], bh[0], bh[1]);
                        }
                    }
                }
            }
            __syncthreads();
        }
    }

    // ---- epilogue ----
#pragma unroll
    for (int m = 0; m < 2; m++) {
        int x0 = m0 + m * 16 + (lane >> 2);
#pragma unroll
        for (int na = 0; na < NA; na++) {
            int n = n0 + na * 8 + 2 * (lane & 3);
            float b0 = __ldg(&bias[n]);
            float b1 = __ldg(&bias[n + 1]);
            if (NHWC_OUT) {
                float* op0 = out + ((size_t)b * HW + (size_t)y * WW + x0) * N_OC + n;
                float* op1 = op0 + 8 * N_OC;
                *(float2*)op0 = make_float2(acc[m][na][0] + b0, acc[m][na][1] + b1);
                *(float2*)op1 = make_float2(acc[m][na][2] + b0, acc[m][na][3] + b1);
            } else {
                size_t base = (size_t)b * N_OC * HW + (size_t)y * WW + x0;
                out[base + (size_t)n * HW]           = acc[m][na][0] + b0;
                out[base + (size_t)(n + 1) * HW]     = acc[m][na][1] + b1;
                out[base + (size_t)n * HW + 8]       = acc[m][na][2] + b0;
                out[base + (size_t)(n + 1) * HW + 8] = acc[m][na][3] + b1;
            }
        }
    }
}

// ---------------------------------------------------------------------------
// Deformable conv v2: 8 K-chunks of ONE deform group (36 word-rows) instead of
// 4 chunks of two -> smem 83KB -> 38KB -> 2x occupancy for the latency-bound
// gather. GEMM per chunk: 4x m16n8k16 + 1x m16n8k8 tail (3-term bf16 split).
// A: [w][px] rows stride 72; B: [w][oc] rows stride 64 (broadcast reads).
// ---------------------------------------------------------------------------
template <bool NCHW_OUT>
__global__ __launch_bounds__(256)
void deform_kernel(const float* __restrict__ src, const float* __restrict__ off,
                   const uint32_t* __restrict__ dwph, const uint32_t* __restrict__ dwpl,
                   const float* __restrict__ bias, float* __restrict__ out)
{
    extern __shared__ __align__(16) uint32_t SM[];
    constexpr int ARST = 72;                  // A row stride (64 px + 8 pad)
    constexpr int BRST = 64;                  // B row stride (broadcast-safe)
    constexpr int A_HI = 0;
    constexpr int A_LO = A_HI + 36 * ARST;
    constexpr int B_HI = A_LO + 36 * ARST;
    constexpr int B_LO = B_HI + 36 * BRST;

    const int tid  = threadIdx.x;
    const int lane = tid & 31;
    const int wid  = tid >> 5;
    const int m0   = (wid & 3) * 16;          // 4 m-tiles of 16 px
    const int n0   = (wid >> 2) * 32;         // 2 n-halves of 32 oc

    const int b   = blockIdx.z;
    const int bx0 = blockIdx.x * 8;
    const int by0 = blockIdx.y * 8;

    float acc[4][4];
#pragma unroll
    for (int na = 0; na < 4; na++)
#pragma unroll
        for (int q = 0; q < 4; q++) acc[na][q] = 0.0f;

    for (int dg = 0; dg < 8; dg++) {
        // ---- stage B: coalesced copy of pre-packed weights (36 x 64) ----
        for (int t = tid; t < 36 * 64; t += 256) {
            int w  = t >> 6;
            int oc = t & 63;
            int g  = ((dg * 36 + w) << 6) + oc;
            int o  = w * BRST + oc;
            SM[B_HI + o] = dwph[g];
            SM[B_LO + o] = dwpl[g];
        }
        // ---- stage A: bilinear gather + bf16 split (9 k x 64 px) ----
        for (int t = tid; t < 576; t += 256) {
            int px = t & 63;
            int k  = t >> 6;               // 0..8

            int yy = by0 + (px >> 3);
            int xx = bx0 + (px & 7);

            int offch = (dg * 9 + k) * 2;
            size_t obase = (((size_t)b * 144 + offch) * HH + yy) * WW + xx;
            float dy = off[obase];
            float dx = off[obase + (size_t)HW];

            float py  = dy + (float)yy + (float)(k / 3 - 1);
            float pxc = dx + (float)xx + (float)(k % 3 - 1);
            float y0f = floorf(py);
            float x0f = floorf(pxc);
            float wy = py - y0f;
            float wx = pxc - x0f;
            int y0 = (int)y0f;
            int x0 = (int)x0f;

            float w00 = (1.0f - wy) * (1.0f - wx);
            float w01 = (1.0f - wy) * wx;
            float w10 = wy * (1.0f - wx);
            float w11 = wy * wx;

            bool vy0 = ((unsigned)y0 < (unsigned)HH);
            bool vy1 = ((unsigned)(y0 + 1) < (unsigned)HH);
            bool vx0 = ((unsigned)x0 < (unsigned)WW);
            bool vx1 = ((unsigned)(x0 + 1) < (unsigned)WW);
            w00 *= (float)(vy0 && vx0);
            w01 *= (float)(vy0 && vx1);
            w10 *= (float)(vy1 && vx0);
            w11 *= (float)(vy1 && vx1);

            int y0c = min(max(y0, 0), HH - 1);
            int y1c = min(max(y0 + 1, 0), HH - 1);
            int x0c = min(max(x0, 0), WW - 1);
            int x1c = min(max(x0 + 1, 0), WW - 1);

            const float* base = src + (size_t)b * HW * 64 + dg * 8;
            const float4* p00 = (const float4*)(base + (size_t)(y0c * WW + x0c) * 64);
            const float4* p01 = (const float4*)(base + (size_t)(y0c * WW + x1c) * 64);
            const float4* p10 = (const float4*)(base + (size_t)(y1c * WW + x0c) * 64);
            const float4* p11 = (const float4*)(base + (size_t)(y1c * WW + x1c) * 64);

            float4 a00 = p00[0], b00 = p00[1];
            float4 a01 = p01[0], b01 = p01[1];
            float4 a10 = p10[0], b10 = p10[1];
            float4 a11 = p11[0], b11 = p11[1];

            float v0 = w00 * a00.x + w01 * a01.x + w10 * a10.x + w11 * a11.x;
            float v1 = w00 * a00.y + w01 * a01.y + w10 * a10.y + w11 * a11.y;
            float v2 = w00 * a00.z + w01 * a01.z + w10 * a10.z + w11 * a11.z;
            float v3 = w00 * a00.w + w01 * a01.w + w10 * a10.w + w11 * a11.w;
            float v4 = w00 * b00.x + w01 * b01.x + w10 * b10.x + w11 * b11.x;
            float v5 = w00 * b00.y + w01 * b01.y + w10 * b10.y + w11 * b11.y;
            float v6 = w00 * b00.z + w01 * b01.z + w10 * b10.z + w11 * b11.z;
            float v7 = w00 * b00.w + w01 * b01.w + w10 * b10.w + w11 * b11.w;

            int w0 = k * 4;                 // word row base
            uint32_t h, l;
            split2(v0, v1, h, l);
            SM[A_HI + (w0 + 0) * ARST + px] = h;
            SM[A_LO + (w0 + 0) * ARST + px] = l;
            split2(v2, v3, h, l);
            SM[A_HI + (w0 + 1) * ARST + px] = h;
            SM[A_LO + (w0 + 1) * ARST + px] = l;
            split2(v4, v5, h, l);
            SM[A_HI + (w0 + 2) * ARST + px] = h;
            SM[A_LO + (w0 + 2) * ARST + px] = l;
            split2(v6, v7, h, l);
            SM[A_HI + (w0 + 3) * ARST + px] = h;
            SM[A_LO + (w0 + 3) * ARST + px] = l;
        }
        __syncthreads();

        // ---- compute: 4 k16 groups + 1 k8 tail of this 72-K chunk ----
        const int rr = lane >> 2;
        const int c  = lane & 3;
#pragma unroll
        for (int g = 0; g < 4; g++) {
            int wA0 = (g * 8 + c) * ARST;
            int wA1 = (g * 8 + c + 4) * ARST;
            int wB0 = (g * 8 + c) * BRST;
            int wB1 = (g * 8 + c + 4) * BRST;
            int row0 = m0 + rr;
            int row1 = m0 + rr + 8;
            uint32_t ah[4], al[4];
            ah[0] = SM[A_HI + wA0 + row0];
            ah[1] = SM[A_HI + wA0 + row1];
            ah[2] = SM[A_HI + wA1 + row0];
            ah[3] = SM[A_HI + wA1 + row1];
            al[0] = SM[A_LO + wA0 + row0];
            al[1] = SM[A_LO + wA0 + row1];
            al[2] = SM[A_LO + wA1 + row0];
            al[3] = SM[A_LO + wA1 + row1];
#pragma unroll
            for (int na = 0; na < 4; na++) {
                int nn = n0 + na * 8 + rr;
                uint32_t bh0 = SM[B_HI + wB0 + nn];
                uint32_t bh1 = SM[B_HI + wB1 + nn];
                uint32_t bl0 = SM[B_LO + wB0 + nn];
                uint32_t bl1 = SM[B_LO + wB1 + nn];
                mma16(acc[na], ah, bh0, bh1);
                mma16(acc[na], ah, bl0, bl1);
                mma16(acc[na], al, bh0, bh1);
            }
        }
        {   // k8 tail: word-rows 32..35 (k = 8)
            int wA = (32 + c) * ARST;
            int wB = (32 + c) * BRST;
            int row0 = m0 + rr;
            int row1 = m0 + rr + 8;
            uint32_t a0h = SM[A_HI + wA + row0];
            uint32_t a1h = SM[A_HI + wA + row1];
            uint32_t a0l = SM[A_LO + wA + row0];
            uint32_t a1l = SM[A_LO + wA + row1];
#pragma unroll
            for (int na = 0; na < 4; na++) {
                int nn = n0 + na * 8 + rr;
                uint32_t bh = SM[B_HI + wB + nn];
                uint32_t bl = SM[B_LO + wB + nn];
                mma8bf(acc[na], a0h, a1h, bh);
                mma8bf(acc[na], a0h, a1h, bl);
                mma8bf(acc[na], a0l, a1l, bh);
            }
        }
        __syncthreads();
    }

    // ---- epilogue ----
    const int rr = lane >> 2;
    const int c  = lane & 3;
#pragma unroll
    for (int na = 0; na < 4; na++) {
        int n = n0 + na * 8 + 2 * c;
        float b0 = __ldg(&bias[n]);
        float b1 = __ldg(&bias[n + 1]);
#pragma unroll
        for (int h = 0; h < 2; h++) {
            int px = m0 + rr + h * 8;
            int y = by0 + (px >> 3);
            int x = bx0 + (px & 7);
            float r0 = acc[na][h * 2 + 0] + b0;
            float r1 = acc[na][h * 2 + 1] + b1;
            if (NCHW_OUT) {
                size_t base = ((size_t)b * 64) * HW + (size_t)y * WW + x;
                out[base + (size_t)n * HW]       = r0;
                out[base + (size_t)(n + 1) * HW] = r1;
            } else {
                *(float2*)&out[((size_t)b * HW + (size_t)y * WW + x) * 64 + n] =
                    make_float2(r0, r1);
            }
        }
    }
}

// ---------------------------------------------------------------------------
extern "C" void kernel_launch(void* const* d_in, const int* in_sizes, int n_in,
                              void* d_out, int out_size)
{
    const float* neibor = (const float*)d_in[0];
    const float* target = (const float*)d_in[1];
    const float* cr_w   = (const float*)d_in[2];
    const float* cr_b   = (const float*)d_in[3];
    const float* off1_w = (const float*)d_in[4];
    const float* off1_b = (const float*)d_in[5];
    const float* d1_w   = (const float*)d_in[6];
    const float* d1_b   = (const float*)d_in[7];
    const float* off2_w = (const float*)d_in[8];
    const float* off2_b = (const float*)d_in[9];
    const float* d2_w   = (const float*)d_in[10];
    const float* d2_b   = (const float*)d_in[11];
    const float* off3_w = (const float*)d_in[12];
    const float* off3_b = (const float*)d_in[13];
    const float* d3_w   = (const float*)d_in[14];
    const float* d3_b   = (const float*)d_in[15];
    const float* off4_w = (const float*)d_in[16];
    const float* off4_b = (const float*)d_in[17];
    const float* d4_w   = (const float*)d_in[18];
    const float* d4_b   = (const float*)d_in[19];
    float* out = (float*)d_out;

    float *bufA, *bufB, *offb, *nhwc128, *nhwcN;
    uint32_t *wph, *wpl, *dwph, *dwpl;
    cudaGetSymbolAddress((void**)&bufA,    g_bufA);
    cudaGetSymbolAddress((void**)&bufB,    g_bufB);
    cudaGetSymbolAddress((void**)&offb,    g_offb);
    cudaGetSymbolAddress((void**)&nhwc128, g_nhwc128);
    cudaGetSymbolAddress((void**)&nhwcN,   g_nhwcN);
    cudaGetSymbolAddress((void**)&wph,     g_wph);
    cudaGetSymbolAddress((void**)&wpl,     g_wpl);
    cudaGetSymbolAddress((void**)&dwph,    g_dwph);
    cudaGetSymbolAddress((void**)&dwpl,    g_dwpl);

    // dynamic smem (bytes)
    const int SM_CR  = (2 * 130 * 20 + 2 * 3 * 64 * 20) * 4;    // 51520
    const int SM_OFF = (2 * 130 * 20 + 2 * 3 * 144 * 20) * 4;   // 89920
    const int SM_DEF = (2 * 36 * 72 + 2 * 36 * 64) * 4;         // 39168
    cudaFuncSetAttribute(conv_mma_kernel<64, 128, true>,
                         cudaFuncAttributeMaxDynamicSharedMemorySize, SM_CR);
    cudaFuncSetAttribute(conv_mma_kernel<144, 64, false>,
                         cudaFuncAttributeMaxDynamicSharedMemorySize, SM_OFF);
    cudaFuncSetAttribute(deform_kernel<false>,
                         cudaFuncAttributeMaxDynamicSharedMemorySize, SM_DEF);
    cudaFuncSetAttribute(deform_kernel<true>,
                         cudaFuncAttributeMaxDynamicSharedMemorySize, SM_DEF);

    dim3 tb(256);
    dim3 dg(WW / 8, HH / 8, NB);                // deform grid
    const int ggrid = NB * HH;                  // 512 conv-GEMM blocks
    const int tgrid = NB * HW / 256;            // transform blocks
    const int WPREP_CR  = (64 * 1152 / 2 + 255) / 256;
    const int WPREP_OFF = (144 * 576 / 2 + 255) / 256;
    const int DWPREP    = (8 * 36 * 64 + 255) / 256;

    // input transforms (independent)
    concat_nhwc128_kernel<<<tgrid, tb>>>(neibor, target, nhwc128);
    nhwc64_kernel<<<tgrid, tb>>>(neibor, nhwcN);

    // 1. fea1 = conv_cr(concat)  -> bufA (NHWC64)
    wprep_kernel<<<WPREP_CR, tb>>>(cr_w, wph, wpl, 128, 64);
    conv_mma_kernel<64, 128, true><<<ggrid, tb, SM_CR>>>(nhwc128, wph, wpl, cr_b, bufA);

    // 2. o1 = off1(fea1) -> offb (NCHW); fea2 = deform(fea1, o1) -> bufB
    wprep_kernel<<<WPREP_OFF, tb>>>(off1_w, wph, wpl, 64, 144);
    conv_mma_kernel<144, 64, false><<<ggrid, tb, SM_OFF>>>(bufA, wph, wpl, off1_b, offb);
    dwprep_kernel<<<DWPREP, tb>>>(d1_w, dwph, dwpl);
    deform_kernel<false><<<dg, tb, SM_DEF>>>(bufA, offb, dwph, dwpl, d1_b, bufB);

    // 3. o2 = off2(fea2); fea3 = deform(fea2, o2) -> bufA
    wprep_kernel<<<WPREP_OFF, tb>>>(off2_w, wph, wpl, 64, 144);
    conv_mma_kernel<144, 64, false><<<ggrid, tb, SM_OFF>>>(bufB, wph, wpl, off2_b, offb);
    dwprep_kernel<<<DWPREP, tb>>>(d2_w, dwph, dwpl);
    deform_kernel<false><<<dg, tb, SM_DEF>>>(bufB, offb, dwph, dwpl, d2_b, bufA);

    // 4. o3 = off3(fea3); fea4 = deform(neibor, o3) -> bufB
    wprep_kernel<<<WPREP_OFF, tb>>>(off3_w, wph, wpl, 64, 144);
    conv_mma_kernel<144, 64, false><<<ggrid, tb, SM_OFF>>>(bufA, wph, wpl, off3_b, offb);
    dwprep_kernel<<<DWPREP, tb>>>(d3_w, dwph, dwpl);
    deform_kernel<false><<<dg, tb, SM_DEF>>>(nhwcN, offb, dwph, dwpl, d3_b, bufB);

    // 5. o4 = off4(fea4); aligned = deform(fea4, o4) -> d_out (NCHW)
    wprep_kernel<<<WPREP_OFF, tb>>>(off4_w, wph, wpl, 64, 144);
    conv_mma_kernel<144, 64, false><<<ggrid, tb, SM_OFF>>>(bufB, wph, wpl, off4_b, offb);
    dwprep_kernel<<<DWPREP, tb>>>(d4_w, dwph, dwpl);
    deform_kernel<true><<<dg, tb, SM_DEF>>>(bufB, offb, dwph, dwpl, d4_b, out);
}

// round 12
// speedup vs baseline: 1.1223x; 1.1223x over previous
#include <cuda_runtime.h>
#include <cuda_bf16.h>
#include <math.h>
#include <stdint.h>

#define HH 128
#define WW 128
#define NB 4
#define HW (HH * WW)

// ---------------- scratch (static device arrays; no allocation) ------------
__device__ float g_bufA[NB * 64 * HW];      // NHWC64 feature buffer
__device__ float g_bufB[NB * 64 * HW];      // NHWC64 feature buffer
__device__ float g_offb[NB * 144 * HW];     // offsets, NCHW
__device__ float g_nhwc128[NB * 128 * HW];  // concat(neibor,target) NHWC128
__device__ float g_nhwcN[NB * 64 * HW];     // neibor NHWC64
__device__ uint32_t g_wph[73728];           // conv weights hi, packed bf16x2 words
__device__ uint32_t g_wpl[73728];           // conv weights lo, packed bf16x2 words
__device__ uint32_t g_dwph[18432];          // deform weights hi, packed
__device__ uint32_t g_dwpl[18432];          // deform weights lo, packed

// ---------------- helpers ---------------------------------------------------
// split a float pair into packed bf16x2 hi word + lo word (even elem low half)
__device__ __forceinline__ void split2(float v0, float v1,
                                       uint32_t& hw, uint32_t& lw) {
    __nv_bfloat16 h0 = __float2bfloat16_rn(v0);
    __nv_bfloat16 h1 = __float2bfloat16_rn(v1);
    float l0 = v0 - __bfloat162float(h0);
    float l1 = v1 - __bfloat162float(h1);
    __nv_bfloat162 hp = __halves2bfloat162(h0, h1);
    __nv_bfloat162 lp = __floats2bfloat162_rn(l0, l1);
    hw = *(uint32_t*)&hp;
    lw = *(uint32_t*)&lp;
}
__device__ __forceinline__ void mma16(float* c, const uint32_t* a,
                                      uint32_t b0, uint32_t b1) {
    asm volatile(
        "mma.sync.aligned.m16n8k16.row.col.f32.bf16.bf16.f32 "
        "{%0,%1,%2,%3}, {%4,%5,%6,%7}, {%8,%9}, {%0,%1,%2,%3};"
        : "+f"(c[0]), "+f"(c[1]), "+f"(c[2]), "+f"(c[3])
        : "r"(a[0]), "r"(a[1]), "r"(a[2]), "r"(a[3]), "r"(b0), "r"(b1));
}
__device__ __forceinline__ void mma8bf(float* c, uint32_t a0, uint32_t a1,
                                       uint32_t b0) {
    asm volatile(
        "mma.sync.aligned.m16n8k8.row.col.f32.bf16.bf16.f32 "
        "{%0,%1,%2,%3}, {%4,%5}, {%6}, {%0,%1,%2,%3};"
        : "+f"(c[0]), "+f"(c[1]), "+f"(c[2]), "+f"(c[3])
        : "r"(a0), "r"(a1), "r"(b0));
}
__device__ __forceinline__ void ldm_x4(uint32_t* r, uint32_t saddr) {
    asm volatile(
        "ldmatrix.sync.aligned.m8n8.x4.shared.b16 {%0,%1,%2,%3}, [%4];"
        : "=r"(r[0]), "=r"(r[1]), "=r"(r[2]), "=r"(r[3]) : "r"(saddr));
}
__device__ __forceinline__ void ldm_x2(uint32_t* r, uint32_t saddr) {
    asm volatile(
        "ldmatrix.sync.aligned.m8n8.x2.shared.b16 {%0,%1}, [%2];"
        : "=r"(r[0]), "=r"(r[1]) : "r"(saddr));
}

// ---------------------------------------------------------------------------
// Transforms
// ---------------------------------------------------------------------------
__global__ __launch_bounds__(256) void concat_nhwc128_kernel(
    const float* __restrict__ n, const float* __restrict__ t, float* __restrict__ out)
{
    int idx = blockIdx.x * 256 + threadIdx.x;   // NB*HW
    int b  = idx >> 14;
    int yx = idx & (HW - 1);
    const float* s0 = n + (size_t)b * 64 * HW + yx;
    const float* s1 = t + (size_t)b * 64 * HW + yx;
    float* o = out + (size_t)idx * 128;
#pragma unroll 8
    for (int c = 0; c < 64; c++) o[c] = s0[(size_t)c * HW];
#pragma unroll 8
    for (int c = 0; c < 64; c++) o[64 + c] = s1[(size_t)c * HW];
}

__global__ __launch_bounds__(256) void nhwc64_kernel(
    const float* __restrict__ in, float* __restrict__ out)
{
    int idx = blockIdx.x * 256 + threadIdx.x;
    int b  = idx >> 14;
    int yx = idx & (HW - 1);
    const float* s = in + (size_t)b * 64 * HW + yx;
    float* o = out + (size_t)idx * 64;
#pragma unroll 8
    for (int c = 0; c < 64; c++) o[c] = s[(size_t)c * HW];
}

// conv weight prep: w[oc][ic][3][3] -> packed bf16x2 hi/lo words laid out as
// [chunk ch][kg][oc][8 words], ch = (kpos, ich), kg = 16-ch half of the chunk.
__global__ void wprep_kernel(const float* __restrict__ w, uint32_t* __restrict__ wph,
                             uint32_t* __restrict__ wpl, int C_IN, int C_OUT)
{
    int i = blockIdx.x * 256 + threadIdx.x;
    int tot = C_OUT * C_IN * 9 / 2;
    if (i >= tot) return;
    int wd = i & 7;
    int t  = i >> 3;
    int oc = t % C_OUT;
    int t2 = t / C_OUT;
    int kg = t2 & 1;
    int ch = t2 >> 1;
    int ICH = C_IN / 32;
    int kpos = ch / ICH;
    int ich  = ch % ICH;
    int ic = ich * 32 + kg * 16 + wd * 2;
    float v0 = w[((size_t)oc * C_IN + ic) * 9 + kpos];
    float v1 = w[((size_t)oc * C_IN + ic + 1) * 9 + kpos];
    uint32_t hw, lw;
    split2(v0, v1, hw, lw);
    wph[i] = hw;
    wpl[i] = lw;
}

// deform weight prep: w[oc][ic][9] -> packed words [(dg*36 + k*4 + wp)*64 + oc]
__global__ void dwprep_kernel(const float* __restrict__ w, uint32_t* __restrict__ dwph,
                              uint32_t* __restrict__ dwpl)
{
    int i = blockIdx.x * 256 + threadIdx.x;
    if (i >= 8 * 36 * 64) return;
    int oc  = i & 63;
    int t   = i >> 6;
    int rem = t % 36;
    int dg  = t / 36;
    int k   = rem >> 2;
    int wp  = rem & 3;
    int ic0 = dg * 8 + wp * 2;
    float v0 = w[((size_t)oc * 64 + ic0) * 9 + k];
    float v1 = w[((size_t)oc * 64 + ic0 + 1) * 9 + k];
    uint32_t hw, lw;
    split2(v0, v1, hw, lw);
    dwph[i] = hw;
    dwpl[i] = lw;
}

// ---------------------------------------------------------------------------
// mma.sync bf16 implicit-GEMM 3x3 conv (unchanged from round 10 — verified win)
// ---------------------------------------------------------------------------
template <int N_OC, int C_IN, bool NHWC_OUT>
__global__ __launch_bounds__(256)
void conv_mma_kernel(const float* __restrict__ in, const uint32_t* __restrict__ wph,
                     const uint32_t* __restrict__ wpl, const float* __restrict__ bias,
                     float* __restrict__ out)
{
    extern __shared__ __align__(16) uint32_t SM[];
    constexpr int ICH  = C_IN / 32;            // ic-chunks per k position
    constexpr int RST  = 20;                   // word row stride
    constexpr int A_HI = 0;
    constexpr int A_LO = A_HI + 130 * RST;
    constexpr int B_HI = A_LO + 130 * RST;
    constexpr int B_LO = B_HI + 3 * N_OC * RST;
    constexpr int NA   = N_OC / 16;            // n-atoms per warp (9 or 4)

    const int tid  = threadIdx.x;
    const int lane = tid & 31;
    const int wid  = tid >> 5;
    const int m0   = (wid & 3) * 32;           // 4 M-tiles of 32 px
    const int n0   = (wid >> 2) * (N_OC / 2);  // 2 N-halves

    const int r = blockIdx.x;
    const int b = r >> 7;
    const int y = r & 127;

    const int quad = lane >> 3;                // ldmatrix lane decode
    const int lr   = lane & 7;

    float acc[2][NA][4];
#pragma unroll
    for (int m = 0; m < 2; m++)
#pragma unroll
        for (int na = 0; na < NA; na++)
#pragma unroll
            for (int q = 0; q < 4; q++) acc[m][na][q] = 0.0f;

    for (int dy = 0; dy < 3; dy++) {
        const int yy = y + dy - 1;
        const bool rv = (yy >= 0) && (yy < HH);

        for (int ich = 0; ich < ICH; ich++) {
            // ---- stage A: 130 px (x = -1..128) x 32 ch, hi/lo split ----
            for (int t = tid; t < 260; t += 256) {
                int p  = t >> 1;
                int kg = t & 1;
                int x  = p - 1;
                bool val = rv && (x >= 0) && (x < WW);
                const float4* src = (const float4*)(in +
                    (((size_t)b * HW + (size_t)yy * WW + x) * C_IN + ich * 32 + kg * 16));
                int abase = p * RST + kg * 8;
#pragma unroll
                for (int j = 0; j < 4; j++) {
                    float4 v = val ? src[j] : make_float4(0.f, 0.f, 0.f, 0.f);
                    uint32_t h0, l0, h1, l1;
                    split2(v.x, v.y, h0, l0);
                    split2(v.z, v.w, h1, l1);
                    *(uint2*)&SM[A_HI + abase + 2 * j] = make_uint2(h0, h1);
                    *(uint2*)&SM[A_LO + abase + 2 * j] = make_uint2(l0, l1);
                }
            }
            // ---- stage B: 3 k-positions of this ich (pre-packed copy) ----
            for (int t = tid; t < 3 * N_OC * 16; t += 256) {
                int kp  = t / (N_OC * 16);
                int rem = t - kp * (N_OC * 16);
                int n   = rem >> 4;
                int w16 = rem & 15;
                int kg  = w16 >> 3;
                int wd  = w16 & 7;
                int gsrc = ((((dy * 3 + kp) * ICH + ich) * 2 + kg) * N_OC + n) * 8 + wd;
                int o = (kp * N_OC + n) * RST + w16;
                SM[B_HI + o] = wph[gsrc];
                SM[B_LO + o] = wpl[gsrc];
            }
            __syncthreads();

            // ---- compute: 3 dx taps x 2 k16 groups ----
#pragma unroll
            for (int dx = 0; dx < 3; dx++) {
#pragma unroll
                for (int kg = 0; kg < 2; kg++) {
                    uint32_t ah[2][4], al[2][4];
#pragma unroll
                    for (int m = 0; m < 2; m++) {
                        int row = m0 + m * 16 + dx + (quad & 1) * 8 + lr;
                        int wi  = row * RST + kg * 8 + (quad >> 1) * 4;
                        ldm_x4(ah[m], (uint32_t)__cvta_generic_to_shared(&SM[A_HI + wi]));
                        ldm_x4(al[m], (uint32_t)__cvta_generic_to_shared(&SM[A_LO + wi]));
                    }
#pragma unroll
                    for (int p2 = 0; p2 < NA - 1; p2 += 2) {
                        int rowb = dx * N_OC + n0 + p2 * 8 + (quad >> 1) * 8 + lr;
                        int wi   = rowb * RST + kg * 8 + (quad & 1) * 4;
                        uint32_t bh[4], bl[4];
                        ldm_x4(bh, (uint32_t)__cvta_generic_to_shared(&SM[B_HI + wi]));
                        ldm_x4(bl, (uint32_t)__cvta_generic_to_shared(&SM[B_LO + wi]));
#pragma unroll
                        for (int m = 0; m < 2; m++) {
                            mma16(acc[m][p2], ah[m], bh[0], bh[1]);
                            mma16(acc[m][p2], ah[m], bl[0], bl[1]);
                            mma16(acc[m][p2], al[m], bh[0], bh[1]);
                            mma16(acc[m][p2 + 1], ah[m], bh[2], bh[3]);
                            mma16(acc[m][p2 + 1], ah[m], bl[2], bl[3]);
                            mma16(acc[m][p2 + 1], al[m], bh[2], bh[3]);
                        }
                    }
                    if (NA & 1) {              // tail n-atom (NA = 9)
                        int p2 = NA - 1;
                        int rowb = dx * N_OC + n0 + p2 * 8 + lr;
                        int wi   = rowb * RST + kg * 8 + (quad & 1) * 4;
                        uint32_t bh[2], bl[2];
                        ldm_x2(bh, (uint32_t)__cvta_generic_to_shared(&SM[B_HI + wi]));
                        ldm_x2(bl, (uint32_t)__cvta_generic_to_shared(&SM[B_LO + wi]));
#pragma unroll
                        for (int m = 0; m < 2; m++) {
                            mma16(acc[m][p2], ah[m], bh[0], bh[1]);
                            mma16(acc[m][p2], ah[m], bl[0], bl[1]);
                            mma16(acc[m][p2], al[m], bh[0], bh[1]);
                        }
                    }
                }
            }
            __syncthreads();
        }
    }

    // ---- epilogue ----
#pragma unroll
    for (int m = 0; m < 2; m++) {
        int x0 = m0 + m * 16 + (lane >> 2);
#pragma unroll
        for (int na = 0; na < NA; na++) {
            int n = n0 + na * 8 + 2 * (lane & 3);
            float b0 = __ldg(&bias[n]);
            float b1 = __ldg(&bias[n + 1]);
            if (NHWC_OUT) {
                float* op0 = out + ((size_t)b * HW + (size_t)y * WW + x0) * N_OC + n;
                float* op1 = op0 + 8 * N_OC;
                *(float2*)op0 = make_float2(acc[m][na][0] + b0, acc[m][na][1] + b1);
                *(float2*)op1 = make_float2(acc[m][na][2] + b0, acc[m][na][3] + b1);
            } else {
                size_t base = (size_t)b * N_OC * HW + (size_t)y * WW + x0;
                out[base + (size_t)n * HW]           = acc[m][na][0] + b0;
                out[base + (size_t)(n + 1) * HW]     = acc[m][na][1] + b1;
                out[base + (size_t)n * HW + 8]       = acc[m][na][2] + b0;
                out[base + (size_t)(n + 1) * HW + 8] = acc[m][na][3] + b1;
            }
        }
    }
}

// ---------------------------------------------------------------------------
// Deformable conv v3: 8 K-chunks of ONE deform group (36 word-rows), smem
// 41.5KB for higher occupancy on the latency-bound gather. BOTH A and B use
// row stride 72 (72 mod 32 = 8 -> bank = 8c + rr + ... : conflict-free; the
// round-11 BRST=64 caused 4-way conflicts on every B read).
// GEMM per chunk: 4x m16n8k16 + 1x m16n8k8 tail (3-term bf16 split).
// ---------------------------------------------------------------------------
template <bool NCHW_OUT>
__global__ __launch_bounds__(256)
void deform_kernel(const float* __restrict__ src, const float* __restrict__ off,
                   const uint32_t* __restrict__ dwph, const uint32_t* __restrict__ dwpl,
                   const float* __restrict__ bias, float* __restrict__ out)
{
    extern __shared__ __align__(16) uint32_t SM[];
    constexpr int RST  = 72;                  // row stride (A and B)
    constexpr int A_HI = 0;
    constexpr int A_LO = A_HI + 36 * RST;
    constexpr int B_HI = A_LO + 36 * RST;
    constexpr int B_LO = B_HI + 36 * RST;

    const int tid  = threadIdx.x;
    const int lane = tid & 31;
    const int wid  = tid >> 5;
    const int m0   = (wid & 3) * 16;          // 4 m-tiles of 16 px
    const int n0   = (wid >> 2) * 32;         // 2 n-halves of 32 oc

    const int b   = blockIdx.z;
    const int bx0 = blockIdx.x * 8;
    const int by0 = blockIdx.y * 8;

    float acc[4][4];
#pragma unroll
    for (int na = 0; na < 4; na++)
#pragma unroll
        for (int q = 0; q < 4; q++) acc[na][q] = 0.0f;

    for (int dg = 0; dg < 8; dg++) {
        // ---- stage B: coalesced copy of pre-packed weights (36 x 64) ----
        for (int t = tid; t < 36 * 64; t += 256) {
            int w  = t >> 6;
            int oc = t & 63;
            int g  = ((dg * 36 + w) << 6) + oc;
            int o  = w * RST + oc;
            SM[B_HI + o] = dwph[g];
            SM[B_LO + o] = dwpl[g];
        }
        // ---- stage A: bilinear gather + bf16 split (9 k x 64 px) ----
        for (int t = tid; t < 576; t += 256) {
            int px = t & 63;
            int k  = t >> 6;               // 0..8

            int yy = by0 + (px >> 3);
            int xx = bx0 + (px & 7);

            int offch = (dg * 9 + k) * 2;
            size_t obase = (((size_t)b * 144 + offch) * HH + yy) * WW + xx;
            float dy = off[obase];
            float dx = off[obase + (size_t)HW];

            float py  = dy + (float)yy + (float)(k / 3 - 1);
            float pxc = dx + (float)xx + (float)(k % 3 - 1);
            float y0f = floorf(py);
            float x0f = floorf(pxc);
            float wy = py - y0f;
            float wx = pxc - x0f;
            int y0 = (int)y0f;
            int x0 = (int)x0f;

            float w00 = (1.0f - wy) * (1.0f - wx);
            float w01 = (1.0f - wy) * wx;
            float w10 = wy * (1.0f - wx);
            float w11 = wy * wx;

            bool vy0 = ((unsigned)y0 < (unsigned)HH);
            bool vy1 = ((unsigned)(y0 + 1) < (unsigned)HH);
            bool vx0 = ((unsigned)x0 < (unsigned)WW);
            bool vx1 = ((unsigned)(x0 + 1) < (unsigned)WW);
            w00 *= (float)(vy0 && vx0);
            w01 *= (float)(vy0 && vx1);
            w10 *= (float)(vy1 && vx0);
            w11 *= (float)(vy1 && vx1);

            int y0c = min(max(y0, 0), HH - 1);
            int y1c = min(max(y0 + 1, 0), HH - 1);
            int x0c = min(max(x0, 0), WW - 1);
            int x1c = min(max(x0 + 1, 0), WW - 1);

            const float* base = src + (size_t)b * HW * 64 + dg * 8;
            const float4* p00 = (const float4*)(base + (size_t)(y0c * WW + x0c) * 64);
            const float4* p01 = (const float4*)(base + (size_t)(y0c * WW + x1c) * 64);
            const float4* p10 = (const float4*)(base + (size_t)(y1c * WW + x0c) * 64);
            const float4* p11 = (const float4*)(base + (size_t)(y1c * WW + x1c) * 64);

            float4 a00 = p00[0], b00 = p00[1];
            float4 a01 = p01[0], b01 = p01[1];
            float4 a10 = p10[0], b10 = p10[1];
            float4 a11 = p11[0], b11 = p11[1];

            float v0 = w00 * a00.x + w01 * a01.x + w10 * a10.x + w11 * a11.x;
            float v1 = w00 * a00.y + w01 * a01.y + w10 * a10.y + w11 * a11.y;
            float v2 = w00 * a00.z + w01 * a01.z + w10 * a10.z + w11 * a11.z;
            float v3 = w00 * a00.w + w01 * a01.w + w10 * a10.w + w11 * a11.w;
            float v4 = w00 * b00.x + w01 * b01.x + w10 * b10.x + w11 * b11.x;
            float v5 = w00 * b00.y + w01 * b01.y + w10 * b10.y + w11 * b11.y;
            float v6 = w00 * b00.z + w01 * b01.z + w10 * b10.z + w11 * b11.z;
            float v7 = w00 * b00.w + w01 * b01.w + w10 * b10.w + w11 * b11.w;

            int w0 = k * 4;                 // word row base
            uint32_t h, l;
            split2(v0, v1, h, l);
            SM[A_HI + (w0 + 0) * RST + px] = h;
            SM[A_LO + (w0 + 0) * RST + px] = l;
            split2(v2, v3, h, l);
            SM[A_HI + (w0 + 1) * RST + px] = h;
            SM[A_LO + (w0 + 1) * RST + px] = l;
            split2(v4, v5, h, l);
            SM[A_HI + (w0 + 2) * RST + px] = h;
            SM[A_LO + (w0 + 2) * RST + px] = l;
            split2(v6, v7, h, l);
            SM[A_HI + (w0 + 3) * RST + px] = h;
            SM[A_LO + (w0 + 3) * RST + px] = l;
        }
        __syncthreads();

        // ---- compute: 4 k16 groups + 1 k8 tail of this 72-K chunk ----
        const int rr = lane >> 2;
        const int c  = lane & 3;
#pragma unroll
        for (int g = 0; g < 4; g++) {
            int wA0 = (g * 8 + c) * RST;
            int wA1 = (g * 8 + c + 4) * RST;
            int row0 = m0 + rr;
            int row1 = m0 + rr + 8;
            uint32_t ah[4], al[4];
            ah[0] = SM[A_HI + wA0 + row0];
            ah[1] = SM[A_HI + wA0 + row1];
            ah[2] = SM[A_HI + wA1 + row0];
            ah[3] = SM[A_HI + wA1 + row1];
            al[0] = SM[A_LO + wA0 + row0];
            al[1] = SM[A_LO + wA0 + row1];
            al[2] = SM[A_LO + wA1 + row0];
            al[3] = SM[A_LO + wA1 + row1];
#pragma unroll
            for (int na = 0; na < 4; na++) {
                int nn = n0 + na * 8 + rr;
                uint32_t bh0 = SM[B_HI + wA0 + nn];
                uint32_t bh1 = SM[B_HI + wA1 + nn];
                uint32_t bl0 = SM[B_LO + wA0 + nn];
                uint32_t bl1 = SM[B_LO + wA1 + nn];
                mma16(acc[na], ah, bh0, bh1);
                mma16(acc[na], ah, bl0, bl1);
                mma16(acc[na], al, bh0, bh1);
            }
        }
        {   // k8 tail: word-rows 32..35 (k = 8)
            int wA = (32 + c) * RST;
            int row0 = m0 + rr;
            int row1 = m0 + rr + 8;
            uint32_t a0h = SM[A_HI + wA + row0];
            uint32_t a1h = SM[A_HI + wA + row1];
            uint32_t a0l = SM[A_LO + wA + row0];
            uint32_t a1l = SM[A_LO + wA + row1];
#pragma unroll
            for (int na = 0; na < 4; na++) {
                int nn = n0 + na * 8 + rr;
                uint32_t bh = SM[B_HI + wA + nn];
                uint32_t bl = SM[B_LO + wA + nn];
                mma8bf(acc[na], a0h, a1h, bh);
                mma8bf(acc[na], a0h, a1h, bl);
                mma8bf(acc[na], a0l, a1l, bh);
            }
        }
        __syncthreads();
    }

    // ---- epilogue ----
    const int rr = lane >> 2;
    const int c  = lane & 3;
#pragma unroll
    for (int na = 0; na < 4; na++) {
        int n = n0 + na * 8 + 2 * c;
        float b0 = __ldg(&bias[n]);
        float b1 = __ldg(&bias[n + 1]);
#pragma unroll
        for (int h = 0; h < 2; h++) {
            int px = m0 + rr + h * 8;
            int y = by0 + (px >> 3);
            int x = bx0 + (px & 7);
            float r0 = acc[na][h * 2 + 0] + b0;
            float r1 = acc[na][h * 2 + 1] + b1;
            if (NCHW_OUT) {
                size_t base = ((size_t)b * 64) * HW + (size_t)y * WW + x;
                out[base + (size_t)n * HW]       = r0;
                out[base + (size_t)(n + 1) * HW] = r1;
            } else {
                *(float2*)&out[((size_t)b * HW + (size_t)y * WW + x) * 64 + n] =
                    make_float2(r0, r1);
            }
        }
    }
}

// ---------------------------------------------------------------------------
extern "C" void kernel_launch(void* const* d_in, const int* in_sizes, int n_in,
                              void* d_out, int out_size)
{
    const float* neibor = (const float*)d_in[0];
    const float* target = (const float*)d_in[1];
    const float* cr_w   = (const float*)d_in[2];
    const float* cr_b   = (const float*)d_in[3];
    const float* off1_w = (const float*)d_in[4];
    const float* off1_b = (const float*)d_in[5];
    const float* d1_w   = (const float*)d_in[6];
    const float* d1_b   = (const float*)d_in[7];
    const float* off2_w = (const float*)d_in[8];
    const float* off2_b = (const float*)d_in[9];
    const float* d2_w   = (const float*)d_in[10];
    const float* d2_b   = (const float*)d_in[11];
    const float* off3_w = (const float*)d_in[12];
    const float* off3_b = (const float*)d_in[13];
    const float* d3_w   = (const float*)d_in[14];
    const float* d3_b   = (const float*)d_in[15];
    const float* off4_w = (const float*)d_in[16];
    const float* off4_b = (const float*)d_in[17];
    const float* d4_w   = (const float*)d_in[18];
    const float* d4_b   = (const float*)d_in[19];
    float* out = (float*)d_out;

    float *bufA, *bufB, *offb, *nhwc128, *nhwcN;
    uint32_t *wph, *wpl, *dwph, *dwpl;
    cudaGetSymbolAddress((void**)&bufA,    g_bufA);
    cudaGetSymbolAddress((void**)&bufB,    g_bufB);
    cudaGetSymbolAddress((void**)&offb,    g_offb);
    cudaGetSymbolAddress((void**)&nhwc128, g_nhwc128);
    cudaGetSymbolAddress((void**)&nhwcN,   g_nhwcN);
    cudaGetSymbolAddress((void**)&wph,     g_wph);
    cudaGetSymbolAddress((void**)&wpl,     g_wpl);
    cudaGetSymbolAddress((void**)&dwph,    g_dwph);
    cudaGetSymbolAddress((void**)&dwpl,    g_dwpl);

    // dynamic smem (bytes)
    const int SM_CR  = (2 * 130 * 20 + 2 * 3 * 64 * 20) * 4;    // 51520
    const int SM_OFF = (2 * 130 * 20 + 2 * 3 * 144 * 20) * 4;   // 89920
    const int SM_DEF = 4 * 36 * 72 * 4;                         // 41472
    cudaFuncSetAttribute(conv_mma_kernel<64, 128, true>,
                         cudaFuncAttributeMaxDynamicSharedMemorySize, SM_CR);
    cudaFuncSetAttribute(conv_mma_kernel<144, 64, false>,
                         cudaFuncAttributeMaxDynamicSharedMemorySize, SM_OFF);
    cudaFuncSetAttribute(deform_kernel<false>,
                         cudaFuncAttributeMaxDynamicSharedMemorySize, SM_DEF);
    cudaFuncSetAttribute(deform_kernel<true>,
                         cudaFuncAttributeMaxDynamicSharedMemorySize, SM_DEF);

    dim3 tb(256);
    dim3 dg(WW / 8, HH / 8, NB);                // deform grid
    const int ggrid = NB * HH;                  // 512 conv-GEMM blocks
    const int tgrid = NB * HW / 256;            // transform blocks
    const int WPREP_CR  = (64 * 1152 / 2 + 255) / 256;
    const int WPREP_OFF = (144 * 576 / 2 + 255) / 256;
    const int DWPREP    = (8 * 36 * 64 + 255) / 256;

    // input transforms (independent)
    concat_nhwc128_kernel<<<tgrid, tb>>>(neibor, target, nhwc128);
    nhwc64_kernel<<<tgrid, tb>>>(neibor, nhwcN);

    // 1. fea1 = conv_cr(concat)  -> bufA (NHWC64)
    wprep_kernel<<<WPREP_CR, tb>>>(cr_w, wph, wpl, 128, 64);
    conv_mma_kernel<64, 128, true><<<ggrid, tb, SM_CR>>>(nhwc128, wph, wpl, cr_b, bufA);

    // 2. o1 = off1(fea1) -> offb (NCHW); fea2 = deform(fea1, o1) -> bufB
    wprep_kernel<<<WPREP_OFF, tb>>>(off1_w, wph, wpl, 64, 144);
    conv_mma_kernel<144, 64, false><<<ggrid, tb, SM_OFF>>>(bufA, wph, wpl, off1_b, offb);
    dwprep_kernel<<<DWPREP, tb>>>(d1_w, dwph, dwpl);
    deform_kernel<false><<<dg, tb, SM_DEF>>>(bufA, offb, dwph, dwpl, d1_b, bufB);

    // 3. o2 = off2(fea2); fea3 = deform(fea2, o2) -> bufA
    wprep_kernel<<<WPREP_OFF, tb>>>(off2_w, wph, wpl, 64, 144);
    conv_mma_kernel<144, 64, false><<<ggrid, tb, SM_OFF>>>(bufB, wph, wpl, off2_b, offb);
    dwprep_kernel<<<DWPREP, tb>>>(d2_w, dwph, dwpl);
    deform_kernel<false><<<dg, tb, SM_DEF>>>(bufB, offb, dwph, dwpl, d2_b, bufA);

    // 4. o3 = off3(fea3); fea4 = deform(neibor, o3) -> bufB
    wprep_kernel<<<WPREP_OFF, tb>>>(off3_w, wph, wpl, 64, 144);
    conv_mma_kernel<144, 64, false><<<ggrid, tb, SM_OFF>>>(bufA, wph, wpl, off3_b, offb);
    dwprep_kernel<<<DWPREP, tb>>>(d3_w, dwph, dwpl);
    deform_kernel<false><<<dg, tb, SM_DEF>>>(nhwcN, offb, dwph, dwpl, d3_b, bufB);

    // 5. o4 = off4(fea4); aligned = deform(fea4, o4) -> d_out (NCHW)
    wprep_kernel<<<WPREP_OFF, tb>>>(off4_w, wph, wpl, 64, 144);
    conv_mma_kernel<144, 64, false><<<ggrid, tb, SM_OFF>>>(bufB, wph, wpl, off4_b, offb);
    dwprep_kernel<<<DWPREP, tb>>>(d4_w, dwph, dwpl);
    deform_kernel<true><<<dg, tb, SM_DEF>>>(bufB, offb, dwph, dwpl, d4_b, out);
}